// round 1
// baseline (speedup 1.0000x reference)
#include <cuda_runtime.h>

// HyperPatch: b=16, c=8, h=w=512, fh=fw=16, c_out=8, sc=64, K=3, PAD=1
// Stage 1: per-patch conv weights  Wpp[n][o] = sum_s w_s2w[o][s] * s[b][s][fy][fx]
//          n = (b*16 + fy)*16 + fx   (4096),  o = ((co*8+ci)*3+i)*3+j  (576)
// Stage 2: per-tile 3x3 conv with reflect padding on the full image.

#define N_TILES 4096
__device__ float g_wpp[N_TILES * 576];   // scratch: [n][o] natural order

// ---------------------------------------------------------------------------
// Kernel 1: C[4096 x 576] = S[4096 x 64] @ w_s2w^T
// grid (32 n-tiles, 72 o-tiles), 128 threads. Each thread: 1 n x 8 o.
// ---------------------------------------------------------------------------
__global__ __launch_bounds__(128) void hyper_weights_kernel(
    const float* __restrict__ w_s2w,   // [576][64]
    const float* __restrict__ s_in)    // [16][64][16][16]
{
    __shared__ float wsm[512];   // 8 rows x 64
    const int t  = threadIdx.x;
    const int o0 = blockIdx.y * 8;

    // coalesced load of 8 consecutive w_s2w rows
#pragma unroll
    for (int i = 0; i < 4; i++)
        wsm[t + i * 128] = w_s2w[o0 * 64 + t + i * 128];
    __syncthreads();

    const int n    = blockIdx.x * 128 + t;
    const int b    = n >> 8;
    const int fyfx = n & 255;
    const float* sp = s_in + b * (64 * 256) + fyfx;

    float acc[8];
#pragma unroll
    for (int k = 0; k < 8; k++) acc[k] = 0.f;

#pragma unroll 8
    for (int s = 0; s < 64; s++) {
        float a = __ldg(sp + s * 256);   // coalesced across lanes (fyfx fast)
#pragma unroll
        for (int k = 0; k < 8; k++)
            acc[k] = fmaf(wsm[k * 64 + s], a, acc[k]);
    }

    float4* dst = reinterpret_cast<float4*>(g_wpp + (size_t)n * 576 + o0);
    dst[0] = make_float4(acc[0], acc[1], acc[2], acc[3]);
    dst[1] = make_float4(acc[4], acc[5], acc[6], acc[7]);
}

// ---------------------------------------------------------------------------
// Kernel 2: per-tile 3x3 conv. grid = 4096 tiles, 128 threads.
// Thread micro-tile: 8 c_out x 8 consecutive pixels in one row.
// smem: input window [8ci][34][36] (stride 36 -> conflict-free float4),
//       weights transposed to [kidx=72][co=8] for LDS.128 broadcast.
// ---------------------------------------------------------------------------
__global__ __launch_bounds__(128, 4) void hyper_conv_kernel(
    const float* __restrict__ x,       // [16][8][512][512]
    float* __restrict__ out)           // [16][8][512][512]
{
    __shared__ float sin_s[8][34][36];
    __shared__ float wsm[72][8];

    const int n  = blockIdx.x;
    const int t  = threadIdx.x;
    const int b  = n >> 8;
    const int fy = (n >> 4) & 15;
    const int fx = n & 15;

    // stage weights: g_wpp[n][co*72 + kidx] -> wsm[kidx][co]
    const float* wpp_n = g_wpp + (size_t)n * 576;
    for (int i = t; i < 576; i += 128) {
        int co   = i / 72;
        int kidx = i - co * 72;
        wsm[kidx][co] = wpp_n[i];
    }

    // stage 34x34x8 reflect-padded input window
    const float* xb  = x + (size_t)b * (8 * 512 * 512);
    const int row0 = fy * 32 - 1;
    const int col0 = fx * 32 - 1;
    for (int i = t; i < 8 * 34 * 34; i += 128) {
        int ci  = i / 1156;
        int rem = i - ci * 1156;
        int r   = rem / 34;
        int cl  = rem - r * 34;
        int gr = row0 + r;  gr = gr < 0 ? -gr : (gr > 511 ? 1022 - gr : gr);
        int gc = col0 + cl; gc = gc < 0 ? -gc : (gc > 511 ? 1022 - gc : gc);
        sin_s[ci][r][cl] = xb[(ci << 18) + (gr << 9) + gc];
    }
    __syncthreads();

    const int py  = t >> 2;          // 0..31
    const int px0 = (t & 3) << 3;    // 0,8,16,24

    float acc[8][8];
#pragma unroll
    for (int co = 0; co < 8; co++)
#pragma unroll
        for (int p = 0; p < 8; p++) acc[co][p] = 0.f;

#pragma unroll 1
    for (int ci = 0; ci < 8; ci++) {
#pragma unroll
        for (int kr = 0; kr < 3; kr++) {
            const float* rowp = &sin_s[ci][py + kr][px0];
            float4 A = *reinterpret_cast<const float4*>(rowp);
            float4 B = *reinterpret_cast<const float4*>(rowp + 4);
            float4 C = *reinterpret_cast<const float4*>(rowp + 8);
            float in[12] = {A.x, A.y, A.z, A.w,
                            B.x, B.y, B.z, B.w,
                            C.x, C.y, C.z, C.w};   // in[10..11] unused
#pragma unroll
            for (int kc = 0; kc < 3; kc++) {
                const float* wr = wsm[ci * 9 + kr * 3 + kc];
                float4 W0 = *reinterpret_cast<const float4*>(wr);
                float4 W1 = *reinterpret_cast<const float4*>(wr + 4);
                float wv[8] = {W0.x, W0.y, W0.z, W0.w,
                               W1.x, W1.y, W1.z, W1.w};
#pragma unroll
                for (int co = 0; co < 8; co++)
#pragma unroll
                    for (int p = 0; p < 8; p++)
                        acc[co][p] = fmaf(wv[co], in[kc + p], acc[co][p]);
            }
        }
    }

    const int gy = (fy << 5) + py;
    const int gx = (fx << 5) + px0;
#pragma unroll
    for (int co = 0; co < 8; co++) {
        float* op = out + (((size_t)(b * 8 + co)) << 18) + (gy << 9) + gx;
        *reinterpret_cast<float4*>(op) =
            make_float4(acc[co][0], acc[co][1], acc[co][2], acc[co][3]);
        *reinterpret_cast<float4*>(op + 4) =
            make_float4(acc[co][4], acc[co][5], acc[co][6], acc[co][7]);
    }
}

// ---------------------------------------------------------------------------
extern "C" void kernel_launch(void* const* d_in, const int* in_sizes, int n_in,
                              void* d_out, int out_size)
{
    (void)in_sizes; (void)n_in; (void)out_size;
    const float* x     = (const float*)d_in[0];   // [16,8,512,512]
    const float* s     = (const float*)d_in[1];   // [16,64,16,16]
    const float* w_s2w = (const float*)d_in[2];   // [576,64]
    float* out = (float*)d_out;                   // [16,8,512,512]

    hyper_weights_kernel<<<dim3(32, 72), 128>>>(w_s2w, s);
    hyper_conv_kernel<<<N_TILES, 128>>>(x, out);
}

// round 3
// speedup vs baseline: 1.0815x; 1.0815x over previous
#include <cuda_runtime.h>

// HyperPatch: b=16, c=8, h=w=512, fh=fw=16, c_out=8, sc=64, K=3, PAD=1
// Stage 1: per-patch conv weights  Wpp[n][o] = sum_s w_s2w[o][s] * s[b][s][fy][fx]
//          n = (b*16 + fy)*16 + fx   (4096),  o = ((co*8+ci)*3+i)*3+j  (576)
// Stage 2: per-tile 3x3 conv with reflect padding, FFMA2 (f32x2) packed over
//          c_out pairs.

#define N_TILES 4096
__device__ float g_wpp[N_TILES * 576];   // scratch: [n][o] natural order

// ---- f32x2 helpers ---------------------------------------------------------
__device__ __forceinline__ unsigned long long ffma2(
    unsigned long long a, unsigned long long b, unsigned long long c)
{
    unsigned long long d;
    asm("fma.rn.f32x2 %0, %1, %2, %3;" : "=l"(d) : "l"(a), "l"(b), "l"(c));
    return d;
}
__device__ __forceinline__ unsigned long long pack2(float x)
{
    unsigned long long d;
    asm("mov.b64 %0, {%1, %1};" : "=l"(d) : "f"(x));
    return d;
}
__device__ __forceinline__ void unpack2(unsigned long long v, float& lo, float& hi)
{
    asm("mov.b64 {%0, %1}, %2;" : "=f"(lo), "=f"(hi) : "l"(v));
}

// ---------------------------------------------------------------------------
// Kernel 1: C[4096 x 576] = S[4096 x 64] @ w_s2w^T
// grid (32 n-tiles, 72 o-tiles), 128 threads. Each thread: 1 n x 8 o.
// ---------------------------------------------------------------------------
__global__ __launch_bounds__(128) void hyper_weights_kernel(
    const float* __restrict__ w_s2w,   // [576][64]
    const float* __restrict__ s_in)    // [16][64][16][16]
{
    __shared__ float wsm[512];   // 8 rows x 64
    const int t  = threadIdx.x;
    const int o0 = blockIdx.y * 8;

#pragma unroll
    for (int i = 0; i < 4; i++)
        wsm[t + i * 128] = w_s2w[o0 * 64 + t + i * 128];
    __syncthreads();

    const int n    = blockIdx.x * 128 + t;
    const int b    = n >> 8;
    const int fyfx = n & 255;
    const float* sp = s_in + b * (64 * 256) + fyfx;

    float acc[8];
#pragma unroll
    for (int k = 0; k < 8; k++) acc[k] = 0.f;

#pragma unroll 8
    for (int s = 0; s < 64; s++) {
        float a = __ldg(sp + s * 256);   // coalesced across lanes (fyfx fast)
#pragma unroll
        for (int k = 0; k < 8; k++)
            acc[k] = fmaf(wsm[k * 64 + s], a, acc[k]);
    }

    float4* dst = reinterpret_cast<float4*>(g_wpp + (size_t)n * 576 + o0);
    dst[0] = make_float4(acc[0], acc[1], acc[2], acc[3]);
    dst[1] = make_float4(acc[4], acc[5], acc[6], acc[7]);
}

// ---------------------------------------------------------------------------
// Kernel 2: per-tile 3x3 conv. grid = 4096 tiles, 128 threads.
// Thread micro-tile: 8 c_out x 8 consecutive pixels, accumulated as
// 4 (co-pair) x 8 px f32x2 registers via fma.rn.f32x2.
// smem: input window [8ci][34][36], weights transposed [kidx=72][co=8]
// (co contiguous -> LDS.128 yields ready (co,co+1) f32x2 pairs).
// ---------------------------------------------------------------------------
__global__ __launch_bounds__(128, 4) void hyper_conv_kernel(
    const float* __restrict__ x,       // [16][8][512][512]
    float* __restrict__ out)           // [16][8][512][512]
{
    __shared__ float sin_s[8][34][36];
    __shared__ __align__(16) float wsm[72][8];

    const int n  = blockIdx.x;
    const int t  = threadIdx.x;
    const int b  = n >> 8;
    const int fy = (n >> 4) & 15;
    const int fx = n & 15;

    // stage weights: g_wpp[n][co*72 + kidx] -> wsm[kidx][co]
    const float* wpp_n = g_wpp + (size_t)n * 576;
    for (int i = t; i < 576; i += 128) {
        int co   = i / 72;
        int kidx = i - co * 72;
        wsm[kidx][co] = wpp_n[i];
    }

    // stage 34x34x8 reflect-padded input window
    const float* xb  = x + (size_t)b * (8 * 512 * 512);
    const int row0 = fy * 32 - 1;
    const int col0 = fx * 32 - 1;
    for (int i = t; i < 8 * 34 * 34; i += 128) {
        int ci  = i / 1156;
        int rem = i - ci * 1156;
        int r   = rem / 34;
        int cl  = rem - r * 34;
        int gr = row0 + r;  gr = gr < 0 ? -gr : (gr > 511 ? 1022 - gr : gr);
        int gc = col0 + cl; gc = gc < 0 ? -gc : (gc > 511 ? 1022 - gc : gc);
        sin_s[ci][r][cl] = xb[(ci << 18) + (gr << 9) + gc];
    }
    __syncthreads();

    const int py  = t >> 2;          // 0..31
    const int px0 = (t & 3) << 3;    // 0,8,16,24

    unsigned long long acc2[4][8];   // [co-pair][pixel] = (co_even, co_odd)
#pragma unroll
    for (int cp = 0; cp < 4; cp++)
#pragma unroll
        for (int p = 0; p < 8; p++) acc2[cp][p] = 0ull;

#pragma unroll 1
    for (int ci = 0; ci < 8; ci++) {
#pragma unroll
        for (int kr = 0; kr < 3; kr++) {
            const float* rowp = &sin_s[ci][py + kr][px0];
            float4 A  = *reinterpret_cast<const float4*>(rowp);
            float4 B  = *reinterpret_cast<const float4*>(rowp + 4);
            float2 Cc = *reinterpret_cast<const float2*>(rowp + 8);
            unsigned long long in2[10];
            in2[0] = pack2(A.x);  in2[1] = pack2(A.y);
            in2[2] = pack2(A.z);  in2[3] = pack2(A.w);
            in2[4] = pack2(B.x);  in2[5] = pack2(B.y);
            in2[6] = pack2(B.z);  in2[7] = pack2(B.w);
            in2[8] = pack2(Cc.x); in2[9] = pack2(Cc.y);
#pragma unroll
            for (int kc = 0; kc < 3; kc++) {
                const ulonglong2* wr =
                    reinterpret_cast<const ulonglong2*>(wsm[ci * 9 + kr * 3 + kc]);
                ulonglong2 wA = wr[0];   // (co0,co1),(co2,co3)
                ulonglong2 wB = wr[1];   // (co4,co5),(co6,co7)
#pragma unroll
                for (int p = 0; p < 8; p++) {
                    acc2[0][p] = ffma2(wA.x, in2[kc + p], acc2[0][p]);
                    acc2[1][p] = ffma2(wA.y, in2[kc + p], acc2[1][p]);
                    acc2[2][p] = ffma2(wB.x, in2[kc + p], acc2[2][p]);
                    acc2[3][p] = ffma2(wB.y, in2[kc + p], acc2[3][p]);
                }
            }
        }
    }

    const int gy = (fy << 5) + py;
    const int gx = (fx << 5) + px0;
#pragma unroll
    for (int cp = 0; cp < 4; cp++) {
        float lo[8], hi[8];
#pragma unroll
        for (int p = 0; p < 8; p++) unpack2(acc2[cp][p], lo[p], hi[p]);
        float* op0 = out + (((size_t)(b * 8 + 2 * cp))     << 18) + (gy << 9) + gx;
        float* op1 = out + (((size_t)(b * 8 + 2 * cp + 1)) << 18) + (gy << 9) + gx;
        *reinterpret_cast<float4*>(op0)     = make_float4(lo[0], lo[1], lo[2], lo[3]);
        *reinterpret_cast<float4*>(op0 + 4) = make_float4(lo[4], lo[5], lo[6], lo[7]);
        *reinterpret_cast<float4*>(op1)     = make_float4(hi[0], hi[1], hi[2], hi[3]);
        *reinterpret_cast<float4*>(op1 + 4) = make_float4(hi[4], hi[5], hi[6], hi[7]);
    }
}

// ---------------------------------------------------------------------------
extern "C" void kernel_launch(void* const* d_in, const int* in_sizes, int n_in,
                              void* d_out, int out_size)
{
    (void)in_sizes; (void)n_in; (void)out_size;
    const float* x     = (const float*)d_in[0];   // [16,8,512,512]
    const float* s     = (const float*)d_in[1];   // [16,64,16,16]
    const float* w_s2w = (const float*)d_in[2];   // [576,64]
    float* out = (float*)d_out;                   // [16,8,512,512]

    hyper_weights_kernel<<<dim3(32, 72), 128>>>(w_s2w, s);
    hyper_conv_kernel<<<N_TILES, 128>>>(x, out);
}

// round 4
// speedup vs baseline: 1.2261x; 1.1337x over previous
#include <cuda_runtime.h>

// HyperPatch: b=16, c=8, h=w=512, fh=fw=16, c_out=8, sc=64, K=3, PAD=1
// Stage 1: per-patch conv weights  Wpp[n][o] = sum_s w_s2w[o][s] * s[b][s][fy][fx]
// Stage 2: per-tile 3x3 conv, reflect padding, f32x2-packed over c_out pairs.
// R3 change: 256 thr/CTA, 4co x 8px micro-tile -> ~64 regs -> 50% occupancy.

#define N_TILES 4096
__device__ float g_wpp[N_TILES * 576];   // scratch: [n][o] natural order

// ---- f32x2 helpers ---------------------------------------------------------
__device__ __forceinline__ unsigned long long ffma2(
    unsigned long long a, unsigned long long b, unsigned long long c)
{
    unsigned long long d;
    asm("fma.rn.f32x2 %0, %1, %2, %3;" : "=l"(d) : "l"(a), "l"(b), "l"(c));
    return d;
}
__device__ __forceinline__ unsigned long long pack2(float x)
{
    unsigned long long d;
    asm("mov.b64 %0, {%1, %1};" : "=l"(d) : "f"(x));
    return d;
}
__device__ __forceinline__ void unpack2(unsigned long long v, float& lo, float& hi)
{
    asm("mov.b64 {%0, %1}, %2;" : "=f"(lo), "=f"(hi) : "l"(v));
}

// ---------------------------------------------------------------------------
// Kernel 1: C[4096 x 576] = S[4096 x 64] @ w_s2w^T
// ---------------------------------------------------------------------------
__global__ __launch_bounds__(128) void hyper_weights_kernel(
    const float* __restrict__ w_s2w,   // [576][64]
    const float* __restrict__ s_in)    // [16][64][16][16]
{
    __shared__ float wsm[512];   // 8 rows x 64
    const int t  = threadIdx.x;
    const int o0 = blockIdx.y * 8;

#pragma unroll
    for (int i = 0; i < 4; i++)
        wsm[t + i * 128] = w_s2w[o0 * 64 + t + i * 128];
    __syncthreads();

    const int n    = blockIdx.x * 128 + t;
    const int b    = n >> 8;
    const int fyfx = n & 255;
    const float* sp = s_in + b * (64 * 256) + fyfx;

    float acc[8];
#pragma unroll
    for (int k = 0; k < 8; k++) acc[k] = 0.f;

#pragma unroll 8
    for (int s = 0; s < 64; s++) {
        float a = __ldg(sp + s * 256);
#pragma unroll
        for (int k = 0; k < 8; k++)
            acc[k] = fmaf(wsm[k * 64 + s], a, acc[k]);
    }

    float4* dst = reinterpret_cast<float4*>(g_wpp + (size_t)n * 576 + o0);
    dst[0] = make_float4(acc[0], acc[1], acc[2], acc[3]);
    dst[1] = make_float4(acc[4], acc[5], acc[6], acc[7]);
}

// ---------------------------------------------------------------------------
// Kernel 2: per-tile 3x3 conv. grid = 4096 tiles, 256 threads.
// Thread micro-tile: 4 c_out (one half, by t>>7) x 8 consecutive pixels,
// accumulated as 2 (co-pair) x 8 px f32x2 registers via fma.rn.f32x2.
// smem: input window [8ci][34][36], weights transposed [kidx=72][co=8].
// ---------------------------------------------------------------------------
__global__ __launch_bounds__(256, 4) void hyper_conv_kernel(
    const float* __restrict__ x,       // [16][8][512][512]
    float* __restrict__ out)           // [16][8][512][512]
{
    __shared__ float sin_s[8][34][36];
    __shared__ __align__(16) float wsm[72][8];

    const int n  = blockIdx.x;
    const int t  = threadIdx.x;
    const int b  = n >> 8;
    const int fy = (n >> 4) & 15;
    const int fx = n & 15;

    // stage weights: g_wpp[n][co*72 + kidx] -> wsm[kidx][co]
    const float* wpp_n = g_wpp + (size_t)n * 576;
    for (int i = t; i < 576; i += 256) {
        int co   = i / 72;
        int kidx = i - co * 72;
        wsm[kidx][co] = wpp_n[i];
    }

    // stage 34x34x8 reflect-padded input window
    const float* xb  = x + (size_t)b * (8 * 512 * 512);
    const int row0 = fy * 32 - 1;
    const int col0 = fx * 32 - 1;
    for (int i = t; i < 8 * 34 * 34; i += 256) {
        int ci  = i / 1156;
        int rem = i - ci * 1156;
        int r   = rem / 34;
        int cl  = rem - r * 34;
        int gr = row0 + r;  gr = gr < 0 ? -gr : (gr > 511 ? 1022 - gr : gr);
        int gc = col0 + cl; gc = gc < 0 ? -gc : (gc > 511 ? 1022 - gc : gc);
        sin_s[ci][r][cl] = xb[(ci << 18) + (gr << 9) + gc];
    }
    __syncthreads();

    const int cohalf = t >> 7;          // 0: co 0-3, 1: co 4-7
    const int tt  = t & 127;
    const int py  = tt >> 2;            // 0..31
    const int px0 = (tt & 3) << 3;      // 0,8,16,24

    unsigned long long acc2[2][8];      // [co-pair within half][pixel]
#pragma unroll
    for (int cp = 0; cp < 2; cp++)
#pragma unroll
        for (int p = 0; p < 8; p++) acc2[cp][p] = 0ull;

#pragma unroll 1
    for (int ci = 0; ci < 8; ci++) {
#pragma unroll
        for (int kr = 0; kr < 3; kr++) {
            const float* rowp = &sin_s[ci][py + kr][px0];
            float4 A  = *reinterpret_cast<const float4*>(rowp);
            float4 B  = *reinterpret_cast<const float4*>(rowp + 4);
            float2 Cc = *reinterpret_cast<const float2*>(rowp + 8);
            unsigned long long in2[10];
            in2[0] = pack2(A.x);  in2[1] = pack2(A.y);
            in2[2] = pack2(A.z);  in2[3] = pack2(A.w);
            in2[4] = pack2(B.x);  in2[5] = pack2(B.y);
            in2[6] = pack2(B.z);  in2[7] = pack2(B.w);
            in2[8] = pack2(Cc.x); in2[9] = pack2(Cc.y);
#pragma unroll
            for (int kc = 0; kc < 3; kc++) {
                const ulonglong2* wr = reinterpret_cast<const ulonglong2*>(
                    &wsm[ci * 9 + kr * 3 + kc][cohalf * 4]);
                ulonglong2 wA = wr[0];   // (co0,co1),(co2,co3) of this half
#pragma unroll
                for (int p = 0; p < 8; p++) {
                    acc2[0][p] = ffma2(wA.x, in2[kc + p], acc2[0][p]);
                    acc2[1][p] = ffma2(wA.y, in2[kc + p], acc2[1][p]);
                }
            }
        }
    }

    const int gy = (fy << 5) + py;
    const int gx = (fx << 5) + px0;
    const int co_base = b * 8 + cohalf * 4;
#pragma unroll
    for (int cp = 0; cp < 2; cp++) {
        float lo[8], hi[8];
#pragma unroll
        for (int p = 0; p < 8; p++) unpack2(acc2[cp][p], lo[p], hi[p]);
        float* op0 = out + (((size_t)(co_base + 2 * cp))     << 18) + (gy << 9) + gx;
        float* op1 = out + (((size_t)(co_base + 2 * cp + 1)) << 18) + (gy << 9) + gx;
        *reinterpret_cast<float4*>(op0)     = make_float4(lo[0], lo[1], lo[2], lo[3]);
        *reinterpret_cast<float4*>(op0 + 4) = make_float4(lo[4], lo[5], lo[6], lo[7]);
        *reinterpret_cast<float4*>(op1)     = make_float4(hi[0], hi[1], hi[2], hi[3]);
        *reinterpret_cast<float4*>(op1 + 4) = make_float4(hi[4], hi[5], hi[6], hi[7]);
    }
}

// ---------------------------------------------------------------------------
extern "C" void kernel_launch(void* const* d_in, const int* in_sizes, int n_in,
                              void* d_out, int out_size)
{
    (void)in_sizes; (void)n_in; (void)out_size;
    const float* x     = (const float*)d_in[0];   // [16,8,512,512]
    const float* s     = (const float*)d_in[1];   // [16,64,16,16]
    const float* w_s2w = (const float*)d_in[2];   // [576,64]
    float* out = (float*)d_out;                   // [16,8,512,512]

    hyper_weights_kernel<<<dim3(32, 72), 128>>>(w_s2w, s);
    hyper_conv_kernel<<<N_TILES, 256>>>(x, out);
}